// round 3
// baseline (speedup 1.0000x reference)
#include <cuda_runtime.h>
#include <cuda_fp16.h>
#include <cstdint>

#define N_C 8192
#define N_E 8192
#define IN_F 256
#define D 128
#define SCALE 0.08838834764831845f  /* 1/sqrt(128) */

#define BM 64            /* rows per block (attn) */
#define BN 128           /* cols per tile (attn) */
#define NT (N_E / BN)    /* 64 tiles */
#define LDH 136          /* attn smem leading dim in halves */
#define LDB (LDH * 2)    /* bytes: 272 */

// -------- device scratch (static: no allocation allowed) --------
__device__ __half gQh[N_C * D];      // pre-scaled
__device__ __half gKh[N_E * D];      // row-major [key][d]
__device__ __half gVt[D * N_E];      // TRANSPOSED [d][key]
__device__ float  gInv[N_C];
__device__ float  gOscratch[N_C * D];

// smem byte offsets for attn kernel
#define QOFF   0
#define KOFF0  17408
#define KOFF1  (17408 + 34816)
#define VOFF0  (17408 + 69632)
#define VOFF1  (17408 + 69632 + 34816)
#define POFF   (17408 + 139264)
#define ROWOFF (POFF + 17408)
#define INVOFF (ROWOFF + 256)
#define SMEM_TOTAL (INVOFF + 256)

// -------- helpers --------
__device__ __forceinline__ uint32_t smem_u32(const void* p) {
    uint32_t a;
    asm("{ .reg .u64 t; cvta.to.shared.u64 t, %1; cvt.u32.u64 %0, t; }" : "=r"(a) : "l"(p));
    return a;
}
__device__ __forceinline__ void cpa16(uint32_t dst, const void* src) {
    asm volatile("cp.async.cg.shared.global [%0], [%1], 16;\n" :: "r"(dst), "l"(src));
}
#define CP_COMMIT() asm volatile("cp.async.commit_group;\n")
#define CP_WAIT1()  asm volatile("cp.async.wait_group 1;\n")

__device__ __forceinline__ void mma16(float* c,
                                      uint32_t a0, uint32_t a1, uint32_t a2, uint32_t a3,
                                      uint32_t b0, uint32_t b1) {
    asm volatile(
        "mma.sync.aligned.m16n8k16.row.col.f32.f16.f16.f32 "
        "{%0,%1,%2,%3}, {%4,%5,%6,%7}, {%8,%9}, {%0,%1,%2,%3};"
        : "+f"(c[0]), "+f"(c[1]), "+f"(c[2]), "+f"(c[3])
        : "r"(a0), "r"(a1), "r"(a2), "r"(a3), "r"(b0), "r"(b1));
}

// ==================== K1: fused projections via fp16 mma ====================
// grid (N/64, 3): y=0 -> Q (scaled), y=1 -> K, y=2 -> V (transposed store)
// 128 threads = 4 warps, each warp: 16 rows x 128 out cols, k=256 in 4 chunks.
#define LDA1 72   /* halves: 64-k chunk + 8 pad (144B rows, conflict-free) */
__global__ __launch_bounds__(128) void proj_kernel(
    const float* __restrict__ embC, const float* __restrict__ embE,
    const float* __restrict__ Wq, const float* __restrict__ bq,
    const float* __restrict__ Wk, const float* __restrict__ bk,
    const float* __restrict__ Wv, const float* __restrict__ bv)
{
    int which = blockIdx.y;
    const float* src = (which == 0) ? embC : embE;
    const float* W   = (which == 0) ? Wq : (which == 1) ? Wk : Wv;
    const float* b   = (which == 0) ? bq : (which == 1) ? bk : bv;
    float oscale     = (which == 0) ? SCALE : 1.0f;

    __shared__ __half sA[64 * LDA1];    // emb chunk [row][k]
    __shared__ __half sBt[128 * LDA1];  // W^T chunk [n][k]
    __shared__ __half sVt[128 * LDA1];  // V staging [d][key]

    int tid = threadIdx.x, lane = tid & 31, wid = tid >> 5;
    int g = lane >> 2, tig = lane & 3;
    int r0 = blockIdx.x * 64;
    int wr0 = wid * 16;

    float acc[16][4];
#pragma unroll
    for (int nf = 0; nf < 16; nf++)
#pragma unroll
        for (int c = 0; c < 4; c++) acc[nf][c] = 0.f;

    for (int ch = 0; ch < 4; ch++) {
        int k0 = ch * 64;
        __syncthreads();
        // emb chunk: 64 rows x 64 k floats -> half
#pragma unroll
        for (int i = 0; i < 8; i++) {
            int idx = tid + i * 128;
            int row = idx >> 4, c4 = (idx & 15) << 2;
            float4 v = *(const float4*)&src[(size_t)(r0 + row) * IN_F + k0 + c4];
            __half tmp[4] = { __float2half(v.x), __float2half(v.y),
                              __float2half(v.z), __float2half(v.w) };
            *(uint2*)&sA[row * LDA1 + c4] = *(const uint2*)tmp;
        }
        // W chunk: 64 k x 128 n floats -> half, stored transposed [n][k]
#pragma unroll
        for (int i = 0; i < 16; i++) {
            int idx = tid + i * 128;
            int k = idx >> 5, n4 = (idx & 31) << 2;
            float4 v = *(const float4*)&W[(size_t)(k0 + k) * D + n4];
            sBt[(n4 + 0) * LDA1 + k] = __float2half(v.x);
            sBt[(n4 + 1) * LDA1 + k] = __float2half(v.y);
            sBt[(n4 + 2) * LDA1 + k] = __float2half(v.z);
            sBt[(n4 + 3) * LDA1 + k] = __float2half(v.w);
        }
        __syncthreads();
#pragma unroll
        for (int ks = 0; ks < 4; ks++) {
            int kb = ks * 16 + 2 * tig;
            uint32_t a0 = *(const uint32_t*)&sA[(wr0 + g) * LDA1 + kb];
            uint32_t a1 = *(const uint32_t*)&sA[(wr0 + 8 + g) * LDA1 + kb];
            uint32_t a2 = *(const uint32_t*)&sA[(wr0 + g) * LDA1 + kb + 8];
            uint32_t a3 = *(const uint32_t*)&sA[(wr0 + 8 + g) * LDA1 + kb + 8];
#pragma unroll
            for (int nf = 0; nf < 16; nf++) {
                uint32_t b0 = *(const uint32_t*)&sBt[(nf * 8 + g) * LDA1 + kb];
                uint32_t b1 = *(const uint32_t*)&sBt[(nf * 8 + g) * LDA1 + kb + 8];
                mma16(acc[nf], a0, a1, a2, a3, b0, b1);
            }
        }
    }

    if (which == 2) {
        // V: stage [d][key] in smem, then coalesced transposed store
#pragma unroll
        for (int nf = 0; nf < 16; nf++) {
            int col = nf * 8 + 2 * tig;
            float2 bb = *(const float2*)&b[col];
            sVt[(col + 0) * LDA1 + wr0 + g]     = __float2half(acc[nf][0] + bb.x);
            sVt[(col + 1) * LDA1 + wr0 + g]     = __float2half(acc[nf][1] + bb.y);
            sVt[(col + 0) * LDA1 + wr0 + 8 + g] = __float2half(acc[nf][2] + bb.x);
            sVt[(col + 1) * LDA1 + wr0 + 8 + g] = __float2half(acc[nf][3] + bb.y);
        }
        __syncthreads();
#pragma unroll
        for (int i = 0; i < 8; i++) {
            int idx = tid + i * 128;
            int d = idx >> 3, k8 = idx & 7;
            uint4 v = *(const uint4*)&sVt[d * LDA1 + k8 * 8];
            *(uint4*)&gVt[(size_t)d * N_E + r0 + k8 * 8] = v;
        }
    } else {
        __half* dst = (which == 0) ? gQh : gKh;
#pragma unroll
        for (int nf = 0; nf < 16; nf++) {
            int col = nf * 8 + 2 * tig;
            float2 bb = *(const float2*)&b[col];
            __half2 h0 = __floats2half2_rn((acc[nf][0] + bb.x) * oscale,
                                           (acc[nf][1] + bb.y) * oscale);
            __half2 h1 = __floats2half2_rn((acc[nf][2] + bb.x) * oscale,
                                           (acc[nf][3] + bb.y) * oscale);
            *(uint32_t*)&dst[(size_t)(r0 + wr0 + g) * D + col]     = *(uint32_t*)&h0;
            *(uint32_t*)&dst[(size_t)(r0 + wr0 + 8 + g) * D + col] = *(uint32_t*)&h1;
        }
    }
}

// ==================== K2: attention main pass (fp16 mma, cp.async pipeline) ===
__global__ __launch_bounds__(256, 1) void attn_kernel(
    const int* __restrict__ mask, float* __restrict__ attn, float* __restrict__ out0)
{
    if (out0 == nullptr) out0 = gOscratch;

    extern __shared__ char sm[];
    uint32_t sb = smem_u32(sm);
    float* sRow = (float*)(sm + ROWOFF);
    float* sInv = (float*)(sm + INVOFF);

    int tid  = threadIdx.x;
    int lane = tid & 31, wid = tid >> 5;
    int g = lane >> 2, tig = lane & 3;
    int wm = wid >> 2, wn = wid & 3;
    int i0 = blockIdx.x * BM;

    if (tid < 64) sRow[tid] = 0.f;

    for (int t = tid; t < 64 * 16; t += 256) {
        int r = t >> 4, cc = t & 15;
        uint4 v = *(const uint4*)&gQh[(size_t)(i0 + r) * D + cc * 8];
        *(uint4*)(sm + QOFF + r * LDB + cc * 16) = v;
    }

    const uint32_t kbuf[2] = { sb + KOFF0, sb + KOFF1 };
    const uint32_t vbuf[2] = { sb + VOFF0, sb + VOFF1 };
#pragma unroll
    for (int k = 0; k < 8; k++) {
        int c = tid + k * 256;
        int row = c >> 4, cc = c & 15;
        cpa16(kbuf[0] + row * LDB + cc * 16, &gKh[(size_t)row * D + cc * 8]);
        cpa16(vbuf[0] + row * LDB + cc * 16, &gVt[(size_t)row * N_E + cc * 8]);
    }
    CP_COMMIT();
#pragma unroll
    for (int k = 0; k < 8; k++) {
        int c = tid + k * 256;
        int row = c >> 4, cc = c & 15;
        cpa16(kbuf[1] + row * LDB + cc * 16, &gKh[(size_t)(BN + row) * D + cc * 8]);
        cpa16(vbuf[1] + row * LDB + cc * 16, &gVt[(size_t)row * N_E + BN + cc * 8]);
    }
    CP_COMMIT();

    float oAcc[2][4][4];
#pragma unroll
    for (int mi = 0; mi < 2; mi++)
#pragma unroll
        for (int ni = 0; ni < 4; ni++)
#pragma unroll
            for (int c = 0; c < 4; c++) oAcc[mi][ni][c] = 0.f;
    float rs[2][2] = { {0.f, 0.f}, {0.f, 0.f} };

    int mrow0 = wm * 32 + g;
    int ncol0 = wn * 32 + 2 * tig;

    for (int jt = 0; jt < NT; jt++) {
        int j0 = jt * BN;
        uint32_t sK = kbuf[jt & 1], sV = vbuf[jt & 1];

        CP_WAIT1();
        __syncthreads();

        int2 mreg[2][4][2];
#pragma unroll
        for (int mi = 0; mi < 2; mi++) {
#pragma unroll
            for (int ni = 0; ni < 4; ni++) {
                size_t gr0 = (size_t)(i0 + mrow0 + mi * 16) * N_E + j0 + ncol0 + ni * 8;
                mreg[mi][ni][0] = *(const int2*)&mask[gr0];
                mreg[mi][ni][1] = *(const int2*)&mask[gr0 + 8 * N_E];
            }
        }

        float sAcc[2][4][4];
#pragma unroll
        for (int mi = 0; mi < 2; mi++)
#pragma unroll
            for (int ni = 0; ni < 4; ni++)
#pragma unroll
                for (int c = 0; c < 4; c++) sAcc[mi][ni][c] = 0.f;

#pragma unroll
        for (int ks = 0; ks < 8; ks++) {
            int kb = (ks * 16 + 2 * tig) * 2;
            uint32_t a[2][4];
#pragma unroll
            for (int mi = 0; mi < 2; mi++) {
                uint32_t ro = (uint32_t)(mrow0 + mi * 16) * LDB;
                a[mi][0] = *(const uint32_t*)(sm + QOFF + ro + kb);
                a[mi][1] = *(const uint32_t*)(sm + QOFF + ro + 8 * LDB + kb);
                a[mi][2] = *(const uint32_t*)(sm + QOFF + ro + kb + 16);
                a[mi][3] = *(const uint32_t*)(sm + QOFF + ro + 8 * LDB + kb + 16);
            }
#pragma unroll
            for (int ni = 0; ni < 4; ni++) {
                uint32_t ro = (uint32_t)(wn * 32 + ni * 8 + g) * LDB;
                uint32_t b0 = *(const uint32_t*)((char*)sm + (sK - sb) + ro + kb);
                uint32_t b1 = *(const uint32_t*)((char*)sm + (sK - sb) + ro + kb + 16);
#pragma unroll
                for (int mi = 0; mi < 2; mi++)
                    mma16(sAcc[mi][ni], a[mi][0], a[mi][1], a[mi][2], a[mi][3], b0, b1);
            }
        }

#pragma unroll
        for (int mi = 0; mi < 2; mi++) {
#pragma unroll
            for (int ni = 0; ni < 4; ni++) {
                int lr = mrow0 + mi * 16;
                int lc = ncol0 + ni * 8;
                float p00 = mreg[mi][ni][0].x ? __expf(sAcc[mi][ni][0]) : 0.f;
                float p01 = mreg[mi][ni][0].y ? __expf(sAcc[mi][ni][1]) : 0.f;
                float p10 = mreg[mi][ni][1].x ? __expf(sAcc[mi][ni][2]) : 0.f;
                float p11 = mreg[mi][ni][1].y ? __expf(sAcc[mi][ni][3]) : 0.f;
                rs[mi][0] += p00 + p01;
                rs[mi][1] += p10 + p11;
                size_t gr0 = (size_t)(i0 + lr) * N_E + j0 + lc;
                *(float2*)&attn[gr0]           = make_float2(p00, p01);
                *(float2*)&attn[gr0 + 8 * N_E] = make_float2(p10, p11);
                __half2 h0 = __floats2half2_rn(p00, p01);
                __half2 h1 = __floats2half2_rn(p10, p11);
                *(uint32_t*)(sm + POFF + lr * LDB + lc * 2)       = *(uint32_t*)&h0;
                *(uint32_t*)(sm + POFF + (lr + 8) * LDB + lc * 2) = *(uint32_t*)&h1;
            }
        }
        __syncthreads();

#pragma unroll
        for (int ks = 0; ks < 8; ks++) {
            int kb = (ks * 16 + 2 * tig) * 2;
            uint32_t a[2][4];
#pragma unroll
            for (int mi = 0; mi < 2; mi++) {
                uint32_t ro = (uint32_t)(mrow0 + mi * 16) * LDB;
                a[mi][0] = *(const uint32_t*)(sm + POFF + ro + kb);
                a[mi][1] = *(const uint32_t*)(sm + POFF + ro + 8 * LDB + kb);
                a[mi][2] = *(const uint32_t*)(sm + POFF + ro + kb + 16);
                a[mi][3] = *(const uint32_t*)(sm + POFF + ro + 8 * LDB + kb + 16);
            }
#pragma unroll
            for (int ni = 0; ni < 4; ni++) {
                uint32_t ro = (uint32_t)(wn * 32 + ni * 8 + g) * LDB;
                uint32_t b0 = *(const uint32_t*)((char*)sm + (sV - sb) + ro + kb);
                uint32_t b1 = *(const uint32_t*)((char*)sm + (sV - sb) + ro + kb + 16);
#pragma unroll
                for (int mi = 0; mi < 2; mi++)
                    mma16(oAcc[mi][ni], a[mi][0], a[mi][1], a[mi][2], a[mi][3], b0, b1);
            }
        }
        __syncthreads();

        if (jt + 2 < NT) {
            int jn = (jt + 2) * BN;
            uint32_t kb2 = kbuf[jt & 1], vb2 = vbuf[jt & 1];
#pragma unroll
            for (int k = 0; k < 8; k++) {
                int c = tid + k * 256;
                int row = c >> 4, cc = c & 15;
                cpa16(kb2 + row * LDB + cc * 16, &gKh[(size_t)(jn + row) * D + cc * 8]);
                cpa16(vb2 + row * LDB + cc * 16, &gVt[(size_t)row * N_E + jn + cc * 8]);
            }
        }
        CP_COMMIT();
    }

#pragma unroll
    for (int mi = 0; mi < 2; mi++) {
#pragma unroll
        for (int h = 0; h < 2; h++) {
            float v = rs[mi][h];
            v += __shfl_xor_sync(0xffffffffu, v, 1);
            v += __shfl_xor_sync(0xffffffffu, v, 2);
            if (tig == 0)
                atomicAdd(&sRow[wm * 32 + mi * 16 + h * 8 + g], v);
        }
    }
    __syncthreads();
    if (tid < 64) {
        float inv = 1.0f / sRow[tid];
        sInv[tid] = inv;
        gInv[i0 + tid] = inv;
    }
    __syncthreads();

#pragma unroll
    for (int mi = 0; mi < 2; mi++) {
        int lr = mrow0 + mi * 16;
        float iv0 = sInv[lr], iv1 = sInv[lr + 8];
#pragma unroll
        for (int ni = 0; ni < 4; ni++) {
            int c = ncol0 + ni * 8;
            *(float2*)&out0[(size_t)(i0 + lr) * D + c] =
                make_float2(oAcc[mi][ni][0] * iv0, oAcc[mi][ni][1] * iv0);
            *(float2*)&out0[(size_t)(i0 + lr + 8) * D + c] =
                make_float2(oAcc[mi][ni][2] * iv1, oAcc[mi][ni][3] * iv1);
        }
    }
}

// ==================== K3: normalize attn (fat grid, HBM-saturating) =========
__global__ __launch_bounds__(256) void norm_kernel(float* __restrict__ attn)
{
    size_t idx4 = (size_t)blockIdx.x * 256 + threadIdx.x;   // exact: no bounds needed
    int row = (int)(idx4 >> 11);                            // 2048 float4 per row
    float inv = __ldg(&gInv[row]);
    float4* a4 = (float4*)attn;
    float4 v = a4[idx4];
    v.x *= inv; v.y *= inv; v.z *= inv; v.w *= inv;
    a4[idx4] = v;
}

// ==================== host ====================
extern "C" void kernel_launch(void* const* d_in, const int* in_sizes, int n_in,
                              void* d_out, int out_size)
{
    const float* embC = (const float*)d_in[0];
    const float* embE = (const float*)d_in[1];
    const int*   mask = (const int*)d_in[2];
    const float* Wq = (const float*)d_in[3];
    const float* bq = (const float*)d_in[4];
    const float* Wk = (const float*)d_in[5];
    const float* bk = (const float*)d_in[6];
    const float* Wv = (const float*)d_in[7];
    const float* bv = (const float*)d_in[8];

    float* base = (float*)d_out;
    long long t2 = (long long)N_C * N_E;

    float* out0;
    float* attn;
    if ((long long)out_size == t2) {
        out0 = nullptr;
        attn = base;
    } else {
        out0 = base;
        attn = base + (long long)N_C * D;
    }

    dim3 pgrid(N_C / 64, 3);
    proj_kernel<<<pgrid, 128>>>(embC, embE, Wq, bq, Wk, bk, Wv, bv);

    static int configured = 0;
    if (!configured) {
        cudaFuncSetAttribute(attn_kernel, cudaFuncAttributeMaxDynamicSharedMemorySize, SMEM_TOTAL);
        configured = 1;
    }
    attn_kernel<<<N_C / BM, 256, SMEM_TOTAL>>>(mask, attn, out0);

    int nblocks = (int)(((size_t)N_C * N_E / 4) / 256);     // 65536
    norm_kernel<<<nblocks, 256>>>(attn);
}